// round 4
// baseline (speedup 1.0000x reference)
#include <cuda_runtime.h>
#include <cstdint>

typedef unsigned long long ull;

#define N_NODES 512
#define FDIM 16
#define PADS 4
#define NSTR (N_NODES + PADS)     // 516: kills the stride-512 bank alias
#define ROWS_PER_BLK 64
#define NTHREADS 256
#define CTHREADS 64
#define CPAIRS 4                  // 512 cols / 64 col-threads / 2 (packed)
#define ROWS_PER_THR 16           // 64 rows / 4 row-groups

__device__ __forceinline__ ull pack2(float lo, float hi) {
    ull r;
    asm("mov.b64 %0, {%1, %2};" : "=l"(r) : "f"(lo), "f"(hi));
    return r;
}
__device__ __forceinline__ void unpack2(ull v, float& lo, float& hi) {
    asm("mov.b64 {%0, %1}, %2;" : "=f"(lo), "=f"(hi) : "l"(v));
}
__device__ __forceinline__ ull fma2(ull a, ull b, ull c) {
    ull d;
    asm("fma.rn.f32x2 %0, %1, %2, %3;" : "=l"(d) : "l"(a), "l"(b), "l"(c));
    return d;
}
__device__ __forceinline__ ull add2(ull a, ull b) {
    ull d;
    asm("add.rn.f32x2 %0, %1, %2;" : "=l"(d) : "l"(a), "l"(b));
    return d;
}

// clip(exp(-0.1*sqrt(max(v, 1e-6))), 0, 1)
__device__ __forceinline__ float gauss1(float v) {
    float t = fmaxf(v, 1e-6f);
    float d;
    asm("sqrt.approx.f32 %0, %1;" : "=f"(d) : "f"(t));
    float x = d * -0.14426950408889634f;   // -0.1 * log2(e)
    float e;
    asm("ex2.approx.f32 %0, %1;" : "=f"(e) : "f"(x));
    return fminf(e, 1.0f);                 // result is always >= 0
}

__global__ void __launch_bounds__(NTHREADS, 1)
npg_kernel(const float* __restrict__ x, const float* __restrict__ msk,
           float* __restrict__ out) {
    // A tile transposed: sA[f][n], padded stride
    __shared__ __align__(16) float sA[FDIM * NSTR];
    __shared__ __align__(16) float sna[N_NODES];

    const int tid = threadIdx.x;
    const int bk  = blockIdx.y;

    // ---- stage A = x * msk into smem (transposed) ----
    const float4* xg = reinterpret_cast<const float4*>(x)
                     + (size_t)bk * (N_NODES * FDIM / 4);
    const float* mg = msk + (size_t)bk * N_NODES;
    #pragma unroll
    for (int it = 0; it < (N_NODES * FDIM / 4) / NTHREADS; it++) {
        int i = tid + it * NTHREADS;       // float4 index
        float4 v = __ldg(&xg[i]);
        int n  = i >> 2;                   // node
        int f0 = (i & 3) << 2;             // feature base
        float m = __ldg(&mg[n]);
        sA[(f0 + 0) * NSTR + n] = v.x * m;
        sA[(f0 + 1) * NSTR + n] = v.y * m;
        sA[(f0 + 2) * NSTR + n] = v.z * m;
        sA[(f0 + 3) * NSTR + n] = v.w * m;
    }
    __syncthreads();

    // ---- na[n] = sum_f A[n][f]^2 ----
    #pragma unroll
    for (int it = 0; it < N_NODES / NTHREADS; it++) {
        int n = tid + it * NTHREADS;
        float s = 0.f;
        #pragma unroll
        for (int f = 0; f < FDIM; f++) {
            float a = sA[f * NSTR + n];
            s = fmaf(a, a, s);
        }
        sna[n] = s;
    }
    __syncthreads();

    const int tx = tid & (CTHREADS - 1);   // col-thread (warp-uniform ty)
    const int ty = tid >> 6;               // row group

    // ---- hold 4 column pairs (8 cols) x 16 features in registers, packed ----
    ull ac2[CPAIRS][FDIM];
    ull nac2[CPAIRS];
    #pragma unroll
    for (int j = 0; j < CPAIRS; j++) {
        int p = tx + CTHREADS * j;         // pair index -> cols 2p, 2p+1
        nac2[j] = *reinterpret_cast<const ull*>(&sna[2 * p]);
        #pragma unroll
        for (int f = 0; f < FDIM; f++)
            ac2[j][f] = *reinterpret_cast<const ull*>(&sA[f * NSTR + 2 * p]);
    }

    const int rowBase = blockIdx.x * ROWS_PER_BLK + ty * ROWS_PER_THR;
    float2* outbk = reinterpret_cast<float2*>(out + (size_t)bk * N_NODES * N_NODES);
    const ull NEG2 = pack2(-2.f, -2.f);

    // ---- stream rows (broadcast smem loads), packed-f32x2 gram accumulation ----
    #pragma unroll 1
    for (int i = 0; i < ROWS_PER_THR; i++) {
        const int r = rowBase + i;
        const float nar = sna[r];          // broadcast
        const ull nar2 = pack2(nar, nar);

        ull acc[CPAIRS], s2[CPAIRS];
        #pragma unroll
        for (int j = 0; j < CPAIRS; j++) {
            acc[j] = 0ULL;                 // packed (0,0)
            s2[j]  = add2(nar2, nac2[j]);  // na_r + na_c (both lanes)
        }

        #pragma unroll
        for (int f = 0; f < FDIM; f++) {
            float a = sA[f * NSTR + r];    // broadcast LDS
            ull a2 = pack2(a, a);
            #pragma unroll
            for (int j = 0; j < CPAIRS; j++)
                acc[j] = fma2(a2, ac2[j][f], acc[j]);   // dot over f, 2 cols/op
        }

        float2* orow = outbk + (size_t)r * (N_NODES / 2);
        #pragma unroll
        for (int j = 0; j < CPAIRS; j++) {
            ull v2 = fma2(acc[j], NEG2, s2[j]);   // na_r - 2*dot + na_c
            float v0, v1;
            unpack2(v2, v0, v1);
            float2 o;
            o.x = gauss1(v0);
            o.y = gauss1(v1);
            orow[tx + CTHREADS * j] = o;          // 512B coalesced per warp
        }
    }
}

extern "C" void kernel_launch(void* const* d_in, const int* in_sizes, int n_in,
                              void* d_out, int out_size) {
    const float* x   = (const float*)d_in[0];   // x_msg_binned (8,64,512,16)
    const float* msk = (const float*)d_in[1];   // msk (8,64,512,1)
    float* out = (float*)d_out;                 // (8,64,512,512,1) fp32

    int bk_total = in_sizes[0] / (N_NODES * FDIM);   // 8*64 = 512
    dim3 grid(N_NODES / ROWS_PER_BLK, bk_total);     // (8, 512)
    npg_kernel<<<grid, NTHREADS>>>(x, msk, out);
}

// round 6
// speedup vs baseline: 1.0475x; 1.0475x over previous
#include <cuda_runtime.h>
#include <cstdint>

typedef unsigned long long ull;

#define N_NODES 512
#define FDIM 16
#define PADS 4
#define NSTR (N_NODES + PADS)     // 516 floats = 2064B/row (16B-aligned rows)
#define NTHREADS 256
#define CTHREADS 64               // col-threads; each owns 4 ADJACENT cols
#define COLS_PER_BLK 256          // 64 threads * 4 cols
#define ROWS_PER_BLK 64
#define ROWS_PER_THR 16           // 4 row groups * 16 rows

__device__ __forceinline__ ull pack2(float lo, float hi) {
    ull r;
    asm("mov.b64 %0, {%1, %2};" : "=l"(r) : "f"(lo), "f"(hi));
    return r;
}
__device__ __forceinline__ void unpack2(ull v, float& lo, float& hi) {
    asm("mov.b64 {%0, %1}, %2;" : "=f"(lo), "=f"(hi) : "l"(v));
}
__device__ __forceinline__ ull fma2(ull a, ull b, ull c) {
    ull d;
    asm("fma.rn.f32x2 %0, %1, %2, %3;" : "=l"(d) : "l"(a), "l"(b), "l"(c));
    return d;
}
__device__ __forceinline__ ull add2(ull a, ull b) {
    ull d;
    asm("add.rn.f32x2 %0, %1, %2;" : "=l"(d) : "l"(a), "l"(b));
    return d;
}

// clip(exp(-0.1*sqrt(max(v, 1e-6))), 0, 1)
__device__ __forceinline__ float gauss1(float v) {
    float t = fmaxf(v, 1e-6f);
    float d;
    asm("sqrt.approx.f32 %0, %1;" : "=f"(d) : "f"(t));
    float x = d * -0.14426950408889634f;   // -0.1 * log2(e)
    float e;
    asm("ex2.approx.f32 %0, %1;" : "=f"(e) : "f"(x));
    return fminf(e, 1.0f);                 // always >= 0
}

__global__ void __launch_bounds__(NTHREADS, 2)
npg_kernel(const float* __restrict__ x, const float* __restrict__ msk,
           float* __restrict__ out) {
    // A tile transposed: sA[f][n], padded stride (kills stride-512 bank alias)
    __shared__ __align__(16) float sA[FDIM * NSTR];
    __shared__ __align__(16) float sna[N_NODES];

    const int tid = threadIdx.x;
    const int bk  = blockIdx.z;

    // ---- stage A = x * msk into smem (transposed) ----
    const float4* xg = reinterpret_cast<const float4*>(x)
                     + (size_t)bk * (N_NODES * FDIM / 4);
    const float* mg = msk + (size_t)bk * N_NODES;
    #pragma unroll
    for (int it = 0; it < (N_NODES * FDIM / 4) / NTHREADS; it++) {
        int i = tid + it * NTHREADS;       // float4 index
        float4 v = __ldg(&xg[i]);
        int n  = i >> 2;                   // node
        int f0 = (i & 3) << 2;             // feature base
        float m = __ldg(&mg[n]);
        sA[(f0 + 0) * NSTR + n] = v.x * m;
        sA[(f0 + 1) * NSTR + n] = v.y * m;
        sA[(f0 + 2) * NSTR + n] = v.z * m;
        sA[(f0 + 3) * NSTR + n] = v.w * m;
    }
    __syncthreads();

    // ---- na[n] = sum_f A[n][f]^2 ----
    #pragma unroll
    for (int it = 0; it < N_NODES / NTHREADS; it++) {
        int n = tid + it * NTHREADS;
        float s = 0.f;
        #pragma unroll
        for (int f = 0; f < FDIM; f++) {
            float a = sA[f * NSTR + n];
            s = fmaf(a, a, s);
        }
        sna[n] = s;
    }
    __syncthreads();

    const int tx = tid & (CTHREADS - 1);   // col-thread
    const int ty = tid >> 6;               // row group (warp-uniform pairs)

    // ---- hold 4 adjacent columns x 16 features in registers (32 ulls) ----
    const int c0 = blockIdx.y * COLS_PER_BLK + 4 * tx;   // 16B-aligned
    ull acA[FDIM], acB[FDIM];
    #pragma unroll
    for (int f = 0; f < FDIM; f++) {
        float4 q = *reinterpret_cast<const float4*>(&sA[f * NSTR + c0]);
        acA[f] = pack2(q.x, q.y);
        acB[f] = pack2(q.z, q.w);
    }
    ull nacA, nacB;
    {
        float4 q = *reinterpret_cast<const float4*>(&sna[c0]);
        nacA = pack2(q.x, q.y);
        nacB = pack2(q.z, q.w);
    }

    const int rowBase = blockIdx.x * ROWS_PER_BLK + ty * ROWS_PER_THR;
    float* outbk = out + (size_t)bk * N_NODES * N_NODES;
    const ull NEG2 = pack2(-2.f, -2.f);

    // ---- stream rows (broadcast smem loads), packed-f32x2 gram ----
    #pragma unroll 1
    for (int i = 0; i < ROWS_PER_THR; i++) {
        const int r = rowBase + i;
        const float nar = sna[r];          // broadcast
        const ull nar2 = pack2(nar, nar);

        ull accA = 0ULL, accB = 0ULL;      // packed (0,0)
        #pragma unroll
        for (int f = 0; f < FDIM; f++) {
            float a = sA[f * NSTR + r];    // broadcast LDS
            ull a2 = pack2(a, a);
            accA = fma2(a2, acA[f], accA);
            accB = fma2(a2, acB[f], accB);
        }

        ull vA = fma2(accA, NEG2, add2(nar2, nacA));   // na_r - 2*dot + na_c
        ull vB = fma2(accB, NEG2, add2(nar2, nacB));
        float v0, v1, v2, v3;
        unpack2(vA, v0, v1);
        unpack2(vB, v2, v3);

        float4 o;
        o.x = gauss1(v0);
        o.y = gauss1(v1);
        o.z = gauss1(v2);
        o.w = gauss1(v3);
        *reinterpret_cast<float4*>(&outbk[(size_t)r * N_NODES + c0]) = o;  // STG.128, 512B/warp
    }
}

extern "C" void kernel_launch(void* const* d_in, const int* in_sizes, int n_in,
                              void* d_out, int out_size) {
    const float* x   = (const float*)d_in[0];   // x_msg_binned (8,64,512,16)
    const float* msk = (const float*)d_in[1];   // msk (8,64,512,1)
    float* out = (float*)d_out;                 // (8,64,512,512,1) fp32

    int bk_total = in_sizes[0] / (N_NODES * FDIM);                  // 512
    dim3 grid(N_NODES / ROWS_PER_BLK, N_NODES / COLS_PER_BLK, bk_total);  // (8,2,512)
    npg_kernel<<<grid, NTHREADS>>>(x, msk, out);
}